// round 9
// baseline (speedup 1.0000x reference)
#include <cuda_runtime.h>
#include <cstdint>

#define BB 4
#define LL 2048
#define HH 8
#define EE 64
#define NEG_BIG (-1000.0f)   // ex2(-1000) == 0

// Q pre-scaled at staging by SCALE * log2(e) * (1+2^-11) (K tf32-truncation
// bias compensation folded in; V's bias compensated in the epilogue).
#define QSCALE 0.18042493576f
#define BIAS_COMP 1.00048828125f

#define QTILE 128
#define KTILE 64

// smem strides (floats)
#define QP_STR 68
#define K_STR  68
#define V_STR  72

#define SQP_OFF 0
#define SQP_FLOATS (QTILE * QP_STR)                   // 8704
#define STAGE_K_OFF 0
#define STAGE_V_OFF (KTILE * K_STR)                   // 4352
#define STAGE_FLOATS (KTILE * K_STR + KTILE * V_STR)  // 8960
#define STAGE0_OFF SQP_FLOATS
#define SMEM_FLOATS (SQP_FLOATS + 2 * STAGE_FLOATS)   // 26624
#define MBAR_OFF (SMEM_FLOATS * 4)                    // byte offset of mbar block
// mbar block: full0, empty0, full1, empty1 (8B each)
#define SMEM_BYTES (MBAR_OFF + 32)

__device__ __forceinline__ uint32_t to_tf32(float x) {
    uint32_t y;
    asm("cvt.rna.tf32.f32 %0, %1;" : "=r"(y) : "f"(x));
    return y;
}
__device__ __forceinline__ float to_tf32f(float x) {
    return __uint_as_float(to_tf32(x));
}
__device__ __forceinline__ float ex2(float x) {
    float y;
    asm("ex2.approx.f32 %0, %1;" : "=f"(y) : "f"(x));
    return y;
}

__device__ __forceinline__ void mma_tf32(float c[4], const uint32_t a[4],
                                         uint32_t b0, uint32_t b1) {
    asm volatile(
        "mma.sync.aligned.m16n8k8.row.col.f32.tf32.tf32.f32 "
        "{%0,%1,%2,%3}, {%4,%5,%6,%7}, {%8,%9}, {%0,%1,%2,%3};\n"
        : "+f"(c[0]), "+f"(c[1]), "+f"(c[2]), "+f"(c[3])
        : "r"(a[0]), "r"(a[1]), "r"(a[2]), "r"(a[3]), "r"(b0), "r"(b1));
}

__device__ __forceinline__ void cp16(uint32_t smem_dst, const float* gptr) {
    asm volatile("cp.async.cg.shared.global [%0], [%1], 16;\n"
                 :: "r"(smem_dst), "l"(gptr));
}
__device__ __forceinline__ void mbar_init(uint32_t addr, uint32_t count) {
    asm volatile("mbarrier.init.shared.b64 [%0], %1;"
                 :: "r"(addr), "r"(count) : "memory");
}
__device__ __forceinline__ void mbar_arrive(uint32_t addr) {
    asm volatile("mbarrier.arrive.shared.b64 _, [%0];"
                 :: "r"(addr) : "memory");
}
// HW-arrives on [addr] once this thread's prior cp.async ops complete.
__device__ __forceinline__ void cp_mbar_arrive(uint32_t addr) {
    asm volatile("cp.async.mbarrier.arrive.noinc.shared::cta.b64 [%0];"
                 :: "r"(addr) : "memory");
}
__device__ __forceinline__ void mbar_wait(uint32_t addr, uint32_t parity) {
    asm volatile(
        "{\n\t"
        ".reg .pred P1;\n\t"
        "WAIT_%=:\n\t"
        "mbarrier.try_wait.parity.acquire.cta.shared::cta.b64 P1, [%0], %1, 0x989680;\n\t"
        "@P1 bra.uni DONE_%=;\n\t"
        "bra.uni WAIT_%=;\n\t"
        "DONE_%=:\n\t"
        "}"
        :: "r"(addr), "r"(parity) : "memory");
}

__global__ __launch_bounds__(128, 2)
void sparse_attn_tc5(const float* __restrict__ Q,
                     const float* __restrict__ K,
                     const float* __restrict__ V,
                     float* __restrict__ Out) {
    extern __shared__ float sm[];
    float* sQP = sm + SQP_OFF;

    const int tid  = threadIdx.x;
    const int warp = tid >> 5;
    const int lane = tid & 31;
    const int g    = lane >> 2;
    const int q    = lane & 3;
    const int m0   = warp * 32;

    const int qt = (int)(gridDim.x - 1u - blockIdx.x);  // heavy tiles first
    const int h  = blockIdx.y;
    const int b  = blockIdx.z;

    const int kt_max = 2 * qt + 1;
    const size_t bh_base = ((size_t)b * LL) * HH + h;

    const uint32_t smem_u32 = (uint32_t)__cvta_generic_to_shared(sm);
    const uint32_t mb_full[2]  = {smem_u32 + MBAR_OFF,      smem_u32 + MBAR_OFF + 16};
    const uint32_t mb_empty[2] = {smem_u32 + MBAR_OFF + 8,  smem_u32 + MBAR_OFF + 24};

    // ---- mbarrier init: full=32 (producer-lane HW arrives), empty=4 (warps) ----
    if (tid == 0) {
        mbar_init(mb_full[0], 32);  mbar_init(mb_empty[0], 4);
        mbar_init(mb_full[1], 32);  mbar_init(mb_empty[1], 4);
    }
    __syncthreads();

    // Warp-wide staging of one k-tile (K+V) into stage s_, then HW-arrive on full.
    // Lane i covers chunks f = lane + 32*i (f>>4 = row, f&15 = 16B chunk).
#define STAGE_KV_W(kt_, s_)                                                      \
    {                                                                            \
        float* stg = sm + STAGE0_OFF + (s_) * STAGE_FLOATS;                      \
        uint32_t kb = (uint32_t)__cvta_generic_to_shared(stg + STAGE_K_OFF);     \
        uint32_t vb = (uint32_t)__cvta_generic_to_shared(stg + STAGE_V_OFF);     \
        _Pragma("unroll 8")                                                      \
        for (int i = 0; i < 32; ++i) {                                           \
            int f = lane + i * 32;                                               \
            int row = f >> 4, c4 = f & 15;                                       \
            const size_t goff = (bh_base + ((size_t)(kt_) * KTILE + row) * HH)   \
                                * EE + c4 * 4;                                   \
            cp16(kb + (uint32_t)(row * K_STR + c4 * 4) * 4u, K + goff);          \
            cp16(vb + (uint32_t)(row * V_STR + c4 * 4) * 4u, V + goff);          \
        }                                                                        \
        cp_mbar_arrive(mb_full[(s_)]);                                           \
    }

    // ---- prologue fills: warp0 -> stage0 (kt=0), warp1 -> stage1 (kt=1) ----
    if (warp == 0) { STAGE_KV_W(0, 0) }
    if (warp == 1) { STAGE_KV_W(1, 1) }

    // ---- stage Q tile (128x64), pre-scaled + tf32-rounded ----
#pragma unroll
    for (int i = 0; i < 16; ++i) {
        int f = tid + i * 128;
        int row = f >> 4, c4 = f & 15;
        const float4 v = *reinterpret_cast<const float4*>(
            Q + ((bh_base + ((size_t)qt * QTILE + row) * HH) * EE) + c4 * 4);
        float4 cv = make_float4(to_tf32f(v.x * QSCALE), to_tf32f(v.y * QSCALE),
                                to_tf32f(v.z * QSCALE), to_tf32f(v.w * QSCALE));
        *reinterpret_cast<float4*>(sQP + row * QP_STR + c4 * 4) = cv;
    }
    __syncthreads();

    // ---- hoist Q fragments ----
    uint32_t qa[2][8][4];
#pragma unroll
    for (int rb = 0; rb < 2; ++rb) {
        const int rr = m0 + 16 * rb + g;
#pragma unroll
        for (int kk = 0; kk < 8; ++kk) {
            qa[rb][kk][0] = __float_as_uint(sQP[rr * QP_STR + 8 * kk + q]);
            qa[rb][kk][1] = __float_as_uint(sQP[(rr + 8) * QP_STR + 8 * kk + q]);
            qa[rb][kk][2] = __float_as_uint(sQP[rr * QP_STR + 8 * kk + q + 4]);
            qa[rb][kk][3] = __float_as_uint(sQP[(rr + 8) * QP_STR + 8 * kk + q + 4]);
        }
    }

    float o[2][8][4];
#pragma unroll
    for (int rb = 0; rb < 2; ++rb)
#pragma unroll
        for (int t = 0; t < 8; ++t) {
            o[rb][t][0] = 0.f; o[rb][t][1] = 0.f;
            o[rb][t][2] = 0.f; o[rb][t][3] = 0.f;
        }
    float l_run[2][2] = {{0.f, 0.f}, {0.f, 0.f}};

    for (int kt = 0; kt <= kt_max; ++kt) {
        const int s  = kt & 1;
        const uint32_t ph = (uint32_t)((kt >> 1) & 1);

        // consume when the stage's data has landed (HW cp arrives)
        mbar_wait(mb_full[s], ph);

        float* stg = sm + STAGE0_OFF + s * STAGE_FLOATS;
        float* sK  = stg + STAGE_K_OFF;
        float* sV  = stg + STAGE_V_OFF;

        const bool active = (kt * KTILE <= qt * QTILE + m0 + 31);
        if (active) {
            // ---- GEMM1 ----
            float sc[2][8][4];
#pragma unroll
            for (int rb = 0; rb < 2; ++rb)
#pragma unroll
                for (int t = 0; t < 8; ++t) {
                    sc[rb][t][0] = 0.f; sc[rb][t][1] = 0.f;
                    sc[rb][t][2] = 0.f; sc[rb][t][3] = 0.f;
                }
#pragma unroll
            for (int kk = 0; kk < 8; ++kk) {
#pragma unroll
                for (int t = 0; t < 8; ++t) {
                    uint32_t b0 = __float_as_uint(sK[(8 * t + g) * K_STR + 8 * kk + q]);
                    uint32_t b1 = __float_as_uint(sK[(8 * t + g) * K_STR + 8 * kk + q + 4]);
                    mma_tf32(sc[0][t], qa[0][kk], b0, b1);
                    mma_tf32(sc[1][t], qa[1][kk], b0, b1);
                }
            }

            // ---- mask fast-path check ----
            const int dmin = qt * QTILE + m0 - (kt * KTILE + 63);
            const int dmax = dmin + 94;
            bool hit = false;
            if (dmax >= 2) {
                const int lo = dmin > 2 ? dmin : 2;
                const int hp = 1 << (31 - __clz(dmax));
                hit = hp >= lo;
            }
            const bool need_mask = hit || (dmin < 0);

            const int jb = kt * KTILE + 2 * q;
#pragma unroll
            for (int rb = 0; rb < 2; ++rb) {
                const int r0 = qt * QTILE + m0 + 16 * rb + g;
                const int r1 = r0 + 8;
                float ls0 = 0.f, ls1 = 0.f;
                if (need_mask) {
#pragma unroll
                    for (int t = 0; t < 8; ++t) {
                        const int j0 = jb + 8 * t, j1 = j0 + 1;
#pragma unroll
                        for (int e = 0; e < 4; ++e) {
                            const int ig = (e < 2) ? r0 : r1;
                            const int jg = (e & 1) ? j1 : j0;
                            const int d  = ig - jg;
                            float x = sc[rb][t][e];
                            if (d >= 2 && (d & (d - 1)) == 0) x = 0.0f;
                            if (d < 0) x = NEG_BIG;
                            sc[rb][t][e] = ex2(x);
                        }
                        ls0 += sc[rb][t][0] + sc[rb][t][1];
                        ls1 += sc[rb][t][2] + sc[rb][t][3];
                    }
                } else {
#pragma unroll
                    for (int t = 0; t < 8; ++t) {
                        sc[rb][t][0] = ex2(sc[rb][t][0]);
                        sc[rb][t][1] = ex2(sc[rb][t][1]);
                        sc[rb][t][2] = ex2(sc[rb][t][2]);
                        sc[rb][t][3] = ex2(sc[rb][t][3]);
                        ls0 += sc[rb][t][0] + sc[rb][t][1];
                        ls1 += sc[rb][t][2] + sc[rb][t][3];
                    }
                }
                l_run[rb][0] += ls0;
                l_run[rb][1] += ls1;

                // P -> warp-private slab (aliases dead Q rows)
                const int pr = m0 + 16 * rb + g;
#pragma unroll
                for (int t = 0; t < 8; ++t) {
                    float2 p01 = make_float2(to_tf32f(sc[rb][t][0]),
                                             to_tf32f(sc[rb][t][1]));
                    float2 p23 = make_float2(to_tf32f(sc[rb][t][2]),
                                             to_tf32f(sc[rb][t][3]));
                    *reinterpret_cast<float2*>(sQP + pr * QP_STR + 8 * t + 2 * q) = p01;
                    *reinterpret_cast<float2*>(sQP + (pr + 8) * QP_STR + 8 * t + 2 * q) = p23;
                }
            }
            __syncwarp();

            // ---- GEMM2 ----
#pragma unroll
            for (int kk = 0; kk < 8; ++kk) {
                uint32_t pa0[4], pa1[4];
                {
                    const int rr = m0 + g;
                    pa0[0] = __float_as_uint(sQP[rr * QP_STR + 8 * kk + q]);
                    pa0[1] = __float_as_uint(sQP[(rr + 8) * QP_STR + 8 * kk + q]);
                    pa0[2] = __float_as_uint(sQP[rr * QP_STR + 8 * kk + q + 4]);
                    pa0[3] = __float_as_uint(sQP[(rr + 8) * QP_STR + 8 * kk + q + 4]);
                    const int rs = rr + 16;
                    pa1[0] = __float_as_uint(sQP[rs * QP_STR + 8 * kk + q]);
                    pa1[1] = __float_as_uint(sQP[(rs + 8) * QP_STR + 8 * kk + q]);
                    pa1[2] = __float_as_uint(sQP[rs * QP_STR + 8 * kk + q + 4]);
                    pa1[3] = __float_as_uint(sQP[(rs + 8) * QP_STR + 8 * kk + q + 4]);
                }
#pragma unroll
                for (int t = 0; t < 8; ++t) {
                    uint32_t b0 = __float_as_uint(sV[(8 * kk + q) * V_STR + 8 * t + g]);
                    uint32_t b1 = __float_as_uint(sV[(8 * kk + q + 4) * V_STR + 8 * t + g]);
                    mma_tf32(o[0][t], pa0, b0, b1);
                    mma_tf32(o[1][t], pa1, b0, b1);
                }
            }
        }
        __syncwarp();                       // all lanes done reading sK/sV
        if (lane == 0) mbar_arrive(mb_empty[s]);

        // rotating producer: warp (kt+2)&3 refills this stage for kt+2
        if (kt + 2 <= kt_max && warp == ((kt + 2) & 3)) {
            mbar_wait(mb_empty[s], ph);     // all 4 warps done reading round ph
            STAGE_KV_W(kt + 2, s)
        }
    }

    // ---- epilogue: deferred l reduction, normalize (+V bias comp), write ----
#pragma unroll
    for (int rb = 0; rb < 2; ++rb) {
        float l0 = l_run[rb][0], l1 = l_run[rb][1];
        l0 += __shfl_xor_sync(0xffffffffu, l0, 1);
        l0 += __shfl_xor_sync(0xffffffffu, l0, 2);
        l1 += __shfl_xor_sync(0xffffffffu, l1, 1);
        l1 += __shfl_xor_sync(0xffffffffu, l1, 2);
        const float inv0 = BIAS_COMP / l0;
        const float inv1 = BIAS_COMP / l1;
        const int r0 = qt * QTILE + m0 + 16 * rb + g;
        const int r1 = r0 + 8;
#pragma unroll
        for (int t = 0; t < 8; ++t) {
            const int col = 8 * t + 2 * q;
            float2 w0 = make_float2(o[rb][t][0] * inv0, o[rb][t][1] * inv0);
            float2 w1 = make_float2(o[rb][t][2] * inv1, o[rb][t][3] * inv1);
            *reinterpret_cast<float2*>(
                Out + ((bh_base + (size_t)r0 * HH) * EE) + col) = w0;
            *reinterpret_cast<float2*>(
                Out + ((bh_base + (size_t)r1 * HH) * EE) + col) = w1;
        }
    }
}

extern "C" void kernel_launch(void* const* d_in, const int* in_sizes, int n_in,
                              void* d_out, int out_size) {
    const float* Qp = (const float*)d_in[0];
    const float* Kp = (const float*)d_in[1];
    const float* Vp = (const float*)d_in[2];
    float* Op = (float*)d_out;

    cudaFuncSetAttribute(sparse_attn_tc5,
                         cudaFuncAttributeMaxDynamicSharedMemorySize, SMEM_BYTES);

    dim3 grid(LL / QTILE, HH, BB);  // (16, 8, 4)
    sparse_attn_tc5<<<grid, 128, SMEM_BYTES>>>(Qp, Kp, Vp, Op);
}

// round 10
// speedup vs baseline: 1.0089x; 1.0089x over previous
#include <cuda_runtime.h>
#include <cstdint>

#define BB 4
#define LL 2048
#define HH 8
#define EE 64
#define NEG_BIG (-1000.0f)   // ex2(-1000) == 0

// Q pre-scaled at staging by SCALE * log2(e) * (1+2^-11) (K tf32-truncation
// bias compensation folded in; V's bias compensated in the epilogue).
#define QSCALE 0.18042493576f
#define BIAS_COMP 1.00048828125f

#define QTILE 128
#define KTILE 64

// smem strides (floats)
#define QP_STR 68
#define K_STR  68
#define V_STR  72

#define SQP_OFF 0
#define SQP_FLOATS (QTILE * QP_STR)                   // 8704
#define STAGE_K_OFF 0
#define STAGE_V_OFF (KTILE * K_STR)                   // 4352
#define STAGE_FLOATS (KTILE * K_STR + KTILE * V_STR)  // 8960
#define STAGE0_OFF SQP_FLOATS
#define SMEM_FLOATS (SQP_FLOATS + 2 * STAGE_FLOATS)   // 26624
#define MBAR_OFF (SMEM_FLOATS * 4)                    // byte offset of mbar block
// mbar block: full0, empty0, full1, empty1 (8B each)
#define SMEM_BYTES (MBAR_OFF + 32)

__device__ __forceinline__ uint32_t to_tf32(float x) {
    uint32_t y;
    asm("cvt.rna.tf32.f32 %0, %1;" : "=r"(y) : "f"(x));
    return y;
}
__device__ __forceinline__ float to_tf32f(float x) {
    return __uint_as_float(to_tf32(x));
}
__device__ __forceinline__ float ex2(float x) {
    float y;
    asm("ex2.approx.f32 %0, %1;" : "=f"(y) : "f"(x));
    return y;
}

__device__ __forceinline__ void mma_tf32(float c[4], const uint32_t a[4],
                                         uint32_t b0, uint32_t b1) {
    asm volatile(
        "mma.sync.aligned.m16n8k8.row.col.f32.tf32.tf32.f32 "
        "{%0,%1,%2,%3}, {%4,%5,%6,%7}, {%8,%9}, {%0,%1,%2,%3};\n"
        : "+f"(c[0]), "+f"(c[1]), "+f"(c[2]), "+f"(c[3])
        : "r"(a[0]), "r"(a[1]), "r"(a[2]), "r"(a[3]), "r"(b0), "r"(b1));
}

__device__ __forceinline__ void cp16(uint32_t smem_dst, const float* gptr) {
    asm volatile("cp.async.cg.shared.global [%0], [%1], 16;\n"
                 :: "r"(smem_dst), "l"(gptr));
}
__device__ __forceinline__ void mbar_init(uint32_t addr, uint32_t count) {
    asm volatile("mbarrier.init.shared.b64 [%0], %1;"
                 :: "r"(addr), "r"(count) : "memory");
}
__device__ __forceinline__ void mbar_arrive(uint32_t addr) {
    asm volatile("mbarrier.arrive.shared.b64 _, [%0];"
                 :: "r"(addr) : "memory");
}
// HW-arrives on [addr] once this thread's prior cp.async ops complete.
__device__ __forceinline__ void cp_mbar_arrive(uint32_t addr) {
    asm volatile("cp.async.mbarrier.arrive.noinc.shared::cta.b64 [%0];"
                 :: "r"(addr) : "memory");
}
__device__ __forceinline__ void mbar_wait(uint32_t addr, uint32_t parity) {
    asm volatile(
        "{\n\t"
        ".reg .pred P1;\n\t"
        "WAIT_%=:\n\t"
        "mbarrier.try_wait.parity.acquire.cta.shared::cta.b64 P1, [%0], %1, 0x989680;\n\t"
        "@P1 bra.uni DONE_%=;\n\t"
        "bra.uni WAIT_%=;\n\t"
        "DONE_%=:\n\t"
        "}"
        :: "r"(addr), "r"(parity) : "memory");
}

__global__ __launch_bounds__(128, 2)
void sparse_attn_tc5(const float* __restrict__ Q,
                     const float* __restrict__ K,
                     const float* __restrict__ V,
                     float* __restrict__ Out) {
    extern __shared__ float sm[];
    float* sQP = sm + SQP_OFF;

    const int tid  = threadIdx.x;
    const int warp = tid >> 5;
    const int lane = tid & 31;
    const int g    = lane >> 2;
    const int q    = lane & 3;
    const int m0   = warp * 32;

    const int qt = (int)(gridDim.x - 1u - blockIdx.x);  // heavy tiles first
    const int h  = blockIdx.y;
    const int b  = blockIdx.z;

    const int kt_max = 2 * qt + 1;
    const size_t bh_base = ((size_t)b * LL) * HH + h;

    const uint32_t smem_u32 = (uint32_t)__cvta_generic_to_shared(sm);
    const uint32_t mb_full[2]  = {smem_u32 + MBAR_OFF,      smem_u32 + MBAR_OFF + 16};
    const uint32_t mb_empty[2] = {smem_u32 + MBAR_OFF + 8,  smem_u32 + MBAR_OFF + 24};

    // ---- mbarrier init: full=32 (producer-lane HW arrives), empty=4 (warps) ----
    if (tid == 0) {
        mbar_init(mb_full[0], 32);  mbar_init(mb_empty[0], 4);
        mbar_init(mb_full[1], 32);  mbar_init(mb_empty[1], 4);
    }
    __syncthreads();

    // Warp-wide staging of one k-tile (K+V) into stage s_, then HW-arrive on full.
    // Lane i covers chunks f = lane + 32*i (f>>4 = row, f&15 = 16B chunk).
#define STAGE_KV_W(kt_, s_)                                                      \
    {                                                                            \
        float* stg = sm + STAGE0_OFF + (s_) * STAGE_FLOATS;                      \
        uint32_t kb = (uint32_t)__cvta_generic_to_shared(stg + STAGE_K_OFF);     \
        uint32_t vb = (uint32_t)__cvta_generic_to_shared(stg + STAGE_V_OFF);     \
        _Pragma("unroll 8")                                                      \
        for (int i = 0; i < 32; ++i) {                                           \
            int f = lane + i * 32;                                               \
            int row = f >> 4, c4 = f & 15;                                       \
            const size_t goff = (bh_base + ((size_t)(kt_) * KTILE + row) * HH)   \
                                * EE + c4 * 4;                                   \
            cp16(kb + (uint32_t)(row * K_STR + c4 * 4) * 4u, K + goff);          \
            cp16(vb + (uint32_t)(row * V_STR + c4 * 4) * 4u, V + goff);          \
        }                                                                        \
        cp_mbar_arrive(mb_full[(s_)]);                                           \
    }

    // ---- prologue fills: warp0 -> stage0 (kt=0), warp1 -> stage1 (kt=1) ----
    if (warp == 0) { STAGE_KV_W(0, 0) }
    if (warp == 1) { STAGE_KV_W(1, 1) }

    // ---- stage Q tile (128x64), pre-scaled + tf32-rounded ----
#pragma unroll
    for (int i = 0; i < 16; ++i) {
        int f = tid + i * 128;
        int row = f >> 4, c4 = f & 15;
        const float4 v = *reinterpret_cast<const float4*>(
            Q + ((bh_base + ((size_t)qt * QTILE + row) * HH) * EE) + c4 * 4);
        float4 cv = make_float4(to_tf32f(v.x * QSCALE), to_tf32f(v.y * QSCALE),
                                to_tf32f(v.z * QSCALE), to_tf32f(v.w * QSCALE));
        *reinterpret_cast<float4*>(sQP + row * QP_STR + c4 * 4) = cv;
    }
    __syncthreads();

    // ---- hoist Q fragments ----
    uint32_t qa[2][8][4];
#pragma unroll
    for (int rb = 0; rb < 2; ++rb) {
        const int rr = m0 + 16 * rb + g;
#pragma unroll
        for (int kk = 0; kk < 8; ++kk) {
            qa[rb][kk][0] = __float_as_uint(sQP[rr * QP_STR + 8 * kk + q]);
            qa[rb][kk][1] = __float_as_uint(sQP[(rr + 8) * QP_STR + 8 * kk + q]);
            qa[rb][kk][2] = __float_as_uint(sQP[rr * QP_STR + 8 * kk + q + 4]);
            qa[rb][kk][3] = __float_as_uint(sQP[(rr + 8) * QP_STR + 8 * kk + q + 4]);
        }
    }

    float o[2][8][4];
#pragma unroll
    for (int rb = 0; rb < 2; ++rb)
#pragma unroll
        for (int t = 0; t < 8; ++t) {
            o[rb][t][0] = 0.f; o[rb][t][1] = 0.f;
            o[rb][t][2] = 0.f; o[rb][t][3] = 0.f;
        }
    float l_run[2][2] = {{0.f, 0.f}, {0.f, 0.f}};

    for (int kt = 0; kt <= kt_max; ++kt) {
        const int s  = kt & 1;
        const uint32_t ph = (uint32_t)((kt >> 1) & 1);

        // consume when the stage's data has landed (HW cp arrives)
        mbar_wait(mb_full[s], ph);

        float* stg = sm + STAGE0_OFF + s * STAGE_FLOATS;
        float* sK  = stg + STAGE_K_OFF;
        float* sV  = stg + STAGE_V_OFF;

        const bool active = (kt * KTILE <= qt * QTILE + m0 + 31);
        if (active) {
            // ---- GEMM1 ----
            float sc[2][8][4];
#pragma unroll
            for (int rb = 0; rb < 2; ++rb)
#pragma unroll
                for (int t = 0; t < 8; ++t) {
                    sc[rb][t][0] = 0.f; sc[rb][t][1] = 0.f;
                    sc[rb][t][2] = 0.f; sc[rb][t][3] = 0.f;
                }
#pragma unroll
            for (int kk = 0; kk < 8; ++kk) {
#pragma unroll
                for (int t = 0; t < 8; ++t) {
                    uint32_t b0 = __float_as_uint(sK[(8 * t + g) * K_STR + 8 * kk + q]);
                    uint32_t b1 = __float_as_uint(sK[(8 * t + g) * K_STR + 8 * kk + q + 4]);
                    mma_tf32(sc[0][t], qa[0][kk], b0, b1);
                    mma_tf32(sc[1][t], qa[1][kk], b0, b1);
                }
            }

            // ---- mask fast-path check ----
            const int dmin = qt * QTILE + m0 - (kt * KTILE + 63);
            const int dmax = dmin + 94;
            bool hit = false;
            if (dmax >= 2) {
                const int lo = dmin > 2 ? dmin : 2;
                const int hp = 1 << (31 - __clz(dmax));
                hit = hp >= lo;
            }
            const bool need_mask = hit || (dmin < 0);

            const int jb = kt * KTILE + 2 * q;
#pragma unroll
            for (int rb = 0; rb < 2; ++rb) {
                const int r0 = qt * QTILE + m0 + 16 * rb + g;
                const int r1 = r0 + 8;
                float ls0 = 0.f, ls1 = 0.f;
                if (need_mask) {
#pragma unroll
                    for (int t = 0; t < 8; ++t) {
                        const int j0 = jb + 8 * t, j1 = j0 + 1;
#pragma unroll
                        for (int e = 0; e < 4; ++e) {
                            const int ig = (e < 2) ? r0 : r1;
                            const int jg = (e & 1) ? j1 : j0;
                            const int d  = ig - jg;
                            float x = sc[rb][t][e];
                            if (d >= 2 && (d & (d - 1)) == 0) x = 0.0f;
                            if (d < 0) x = NEG_BIG;
                            sc[rb][t][e] = ex2(x);
                        }
                        ls0 += sc[rb][t][0] + sc[rb][t][1];
                        ls1 += sc[rb][t][2] + sc[rb][t][3];
                    }
                } else {
#pragma unroll
                    for (int t = 0; t < 8; ++t) {
                        sc[rb][t][0] = ex2(sc[rb][t][0]);
                        sc[rb][t][1] = ex2(sc[rb][t][1]);
                        sc[rb][t][2] = ex2(sc[rb][t][2]);
                        sc[rb][t][3] = ex2(sc[rb][t][3]);
                        ls0 += sc[rb][t][0] + sc[rb][t][1];
                        ls1 += sc[rb][t][2] + sc[rb][t][3];
                    }
                }
                l_run[rb][0] += ls0;
                l_run[rb][1] += ls1;

                // P -> warp-private slab (aliases dead Q rows)
                const int pr = m0 + 16 * rb + g;
#pragma unroll
                for (int t = 0; t < 8; ++t) {
                    float2 p01 = make_float2(to_tf32f(sc[rb][t][0]),
                                             to_tf32f(sc[rb][t][1]));
                    float2 p23 = make_float2(to_tf32f(sc[rb][t][2]),
                                             to_tf32f(sc[rb][t][3]));
                    *reinterpret_cast<float2*>(sQP + pr * QP_STR + 8 * t + 2 * q) = p01;
                    *reinterpret_cast<float2*>(sQP + (pr + 8) * QP_STR + 8 * t + 2 * q) = p23;
                }
            }
            __syncwarp();

            // ---- GEMM2 ----
#pragma unroll
            for (int kk = 0; kk < 8; ++kk) {
                uint32_t pa0[4], pa1[4];
                {
                    const int rr = m0 + g;
                    pa0[0] = __float_as_uint(sQP[rr * QP_STR + 8 * kk + q]);
                    pa0[1] = __float_as_uint(sQP[(rr + 8) * QP_STR + 8 * kk + q]);
                    pa0[2] = __float_as_uint(sQP[rr * QP_STR + 8 * kk + q + 4]);
                    pa0[3] = __float_as_uint(sQP[(rr + 8) * QP_STR + 8 * kk + q + 4]);
                    const int rs = rr + 16;
                    pa1[0] = __float_as_uint(sQP[rs * QP_STR + 8 * kk + q]);
                    pa1[1] = __float_as_uint(sQP[(rs + 8) * QP_STR + 8 * kk + q]);
                    pa1[2] = __float_as_uint(sQP[rs * QP_STR + 8 * kk + q + 4]);
                    pa1[3] = __float_as_uint(sQP[(rs + 8) * QP_STR + 8 * kk + q + 4]);
                }
#pragma unroll
                for (int t = 0; t < 8; ++t) {
                    uint32_t b0 = __float_as_uint(sV[(8 * kk + q) * V_STR + 8 * t + g]);
                    uint32_t b1 = __float_as_uint(sV[(8 * kk + q + 4) * V_STR + 8 * t + g]);
                    mma_tf32(o[0][t], pa0, b0, b1);
                    mma_tf32(o[1][t], pa1, b0, b1);
                }
            }
        }
        __syncwarp();                       // all lanes done reading sK/sV
        if (lane == 0) mbar_arrive(mb_empty[s]);

        // rotating producer: warp (kt+2)&3 refills this stage for kt+2
        if (kt + 2 <= kt_max && warp == ((kt + 2) & 3)) {
            mbar_wait(mb_empty[s], ph);     // all 4 warps done reading round ph
            STAGE_KV_W(kt + 2, s)
        }
    }

    // ---- epilogue: deferred l reduction, normalize (+V bias comp), write ----
#pragma unroll
    for (int rb = 0; rb < 2; ++rb) {
        float l0 = l_run[rb][0], l1 = l_run[rb][1];
        l0 += __shfl_xor_sync(0xffffffffu, l0, 1);
        l0 += __shfl_xor_sync(0xffffffffu, l0, 2);
        l1 += __shfl_xor_sync(0xffffffffu, l1, 1);
        l1 += __shfl_xor_sync(0xffffffffu, l1, 2);
        const float inv0 = BIAS_COMP / l0;
        const float inv1 = BIAS_COMP / l1;
        const int r0 = qt * QTILE + m0 + 16 * rb + g;
        const int r1 = r0 + 8;
#pragma unroll
        for (int t = 0; t < 8; ++t) {
            const int col = 8 * t + 2 * q;
            float2 w0 = make_float2(o[rb][t][0] * inv0, o[rb][t][1] * inv0);
            float2 w1 = make_float2(o[rb][t][2] * inv1, o[rb][t][3] * inv1);
            *reinterpret_cast<float2*>(
                Out + ((bh_base + (size_t)r0 * HH) * EE) + col) = w0;
            *reinterpret_cast<float2*>(
                Out + ((bh_base + (size_t)r1 * HH) * EE) + col) = w1;
        }
    }
}

extern "C" void kernel_launch(void* const* d_in, const int* in_sizes, int n_in,
                              void* d_out, int out_size) {
    const float* Qp = (const float*)d_in[0];
    const float* Kp = (const float*)d_in[1];
    const float* Vp = (const float*)d_in[2];
    float* Op = (float*)d_out;

    cudaFuncSetAttribute(sparse_attn_tc5,
                         cudaFuncAttributeMaxDynamicSharedMemorySize, SMEM_BYTES);

    dim3 grid(LL / QTILE, HH, BB);  // (16, 8, 4)
    sparse_attn_tc5<<<grid, 128, SMEM_BYTES>>>(Qp, Kp, Vp, Op);
}